// round 5
// baseline (speedup 1.0000x reference)
#include <cuda_runtime.h>
#include <cuda_bf16.h>
#include <math.h>

#define UU 100000
#define BB 128
#define KK 500
#define KPAD 512
#define NNBH 100
#define NRUNS 10

// ---------------- scratch (no allocations allowed) ----------------
__device__ float  g_y[NRUNS][KPAD][BB];   // centered+normalized rows; rows >=500 zero
__device__ float2 g_pos[NRUNS][KPAD];
__device__ double g_acc[NRUNS][5];        // Sr, Srr, Srd, Sd, Sdd

// ---------------- threefry2x32 (JAX legacy layout — validated R2) ----------------
__device__ __forceinline__ unsigned rotl32(unsigned x, int r) {
    return (x << r) | (x >> (32 - r));
}

__device__ __forceinline__ void tf2x32(unsigned x0, unsigned x1,
                                       unsigned& o0, unsigned& o1) {
    const unsigned k0 = 0u, k1 = 42u;
    const unsigned k2 = k0 ^ k1 ^ 0x1BD11BDAu;
    x0 += k0; x1 += k1;
    const int rotA[4] = {13, 15, 26, 6};
    const int rotB[4] = {17, 29, 16, 24};
#pragma unroll
    for (int i = 0; i < 4; i++) { x0 += x1; x1 = rotl32(x1, rotA[i]); x1 ^= x0; }
    x0 += k1; x1 += k2 + 1u;
#pragma unroll
    for (int i = 0; i < 4; i++) { x0 += x1; x1 = rotl32(x1, rotB[i]); x1 ^= x0; }
    x0 += k2; x1 += k0 + 2u;
#pragma unroll
    for (int i = 0; i < 4; i++) { x0 += x1; x1 = rotl32(x1, rotA[i]); x1 ^= x0; }
    x0 += k0; x1 += k1 + 3u;
#pragma unroll
    for (int i = 0; i < 4; i++) { x0 += x1; x1 = rotl32(x1, rotB[i]); x1 ^= x0; }
    x0 += k1; x1 += k2 + 4u;
#pragma unroll
    for (int i = 0; i < 4; i++) { x0 += x1; x1 = rotl32(x1, rotA[i]); x1 ^= x0; }
    x0 += k2; x1 += k0 + 5u;
    o0 = x0; o1 = x1;
}

__device__ __forceinline__ unsigned choice_for(int r) {
    unsigned a0, a1;
    tf2x32((unsigned)r, (unsigned)(r + NRUNS), a0, a1);
    return ((a0 % 100u) * 96u + (a1 % 100u)) % 100u;   // (2^16%100)^2%100 = 96
}

// ---------------- kernel 1: gather + center + normalize ----------------
// grid (32, NRUNS) x 256. Each warp handles 2 k's with all 8 feature loads
// batched back-to-back for queue depth. k in [500,512) writes zero pad rows.
__global__ void __launch_bounds__(256) k_gather(const float* __restrict__ feats,
                                                const float* __restrict__ pos,
                                                const int* __restrict__ neigh) {
    int run = blockIdx.y;
    __shared__ int s_choice;
    if (threadIdx.x == 0) s_choice = (int)choice_for(run);
    if (blockIdx.x == 0 && threadIdx.x < 5) g_acc[run][threadIdx.x] = 0.0;
    __syncthreads();
    int choice = s_choice;
    int warp = threadIdx.x >> 5, lane = threadIdx.x & 31;
    int k0 = blockIdx.x * 16 + warp * 2;
    int k1 = k0 + 1;

    int u0 = (k0 < KK) ? __ldg(&neigh[choice * KK + k0]) : -1;
    int u1 = (k1 < KK) ? __ldg(&neigh[choice * KK + k1]) : -1;

    // batch all 8 scattered loads
    float a0 = 0.f, a1 = 0.f, a2 = 0.f, a3 = 0.f;
    float b0 = 0.f, b1 = 0.f, b2 = 0.f, b3 = 0.f;
    if (u0 >= 0) {
        a0 = __ldg(&feats[(size_t)(lane      ) * UU + u0]);
        a1 = __ldg(&feats[(size_t)(lane + 32) * UU + u0]);
        a2 = __ldg(&feats[(size_t)(lane + 64) * UU + u0]);
        a3 = __ldg(&feats[(size_t)(lane + 96) * UU + u0]);
    }
    if (u1 >= 0) {
        b0 = __ldg(&feats[(size_t)(lane      ) * UU + u1]);
        b1 = __ldg(&feats[(size_t)(lane + 32) * UU + u1]);
        b2 = __ldg(&feats[(size_t)(lane + 64) * UU + u1]);
        b3 = __ldg(&feats[(size_t)(lane + 96) * UU + u1]);
    }

    // k0
    {
        float s = a0 + a1 + a2 + a3;
#pragma unroll
        for (int o = 16; o; o >>= 1) s += __shfl_xor_sync(0xFFFFFFFFu, s, o);
        float mean = s * (1.0f / 128.0f);
        float c0 = a0 - mean, c1 = a1 - mean, c2 = a2 - mean, c3 = a3 - mean;
        float ss = c0 * c0 + c1 * c1 + c2 * c2 + c3 * c3;
#pragma unroll
        for (int o = 16; o; o >>= 1) ss += __shfl_xor_sync(0xFFFFFFFFu, ss, o);
        float inv = (u0 >= 0) ? rsqrtf(ss) : 0.0f;
        g_y[run][k0][lane     ] = c0 * inv;
        g_y[run][k0][lane + 32] = c1 * inv;
        g_y[run][k0][lane + 64] = c2 * inv;
        g_y[run][k0][lane + 96] = c3 * inv;
        if (lane == 0)
            g_pos[run][k0] = (u0 >= 0) ? ((const float2*)pos)[u0] : make_float2(0.f, 0.f);
    }
    // k1
    {
        float s = b0 + b1 + b2 + b3;
#pragma unroll
        for (int o = 16; o; o >>= 1) s += __shfl_xor_sync(0xFFFFFFFFu, s, o);
        float mean = s * (1.0f / 128.0f);
        float c0 = b0 - mean, c1 = b1 - mean, c2 = b2 - mean, c3 = b3 - mean;
        float ss = c0 * c0 + c1 * c1 + c2 * c2 + c3 * c3;
#pragma unroll
        for (int o = 16; o; o >>= 1) ss += __shfl_xor_sync(0xFFFFFFFFu, ss, o);
        float inv = (u1 >= 0) ? rsqrtf(ss) : 0.0f;
        g_y[run][k1][lane     ] = c0 * inv;
        g_y[run][k1][lane + 32] = c1 * inv;
        g_y[run][k1][lane + 64] = c2 * inv;
        g_y[run][k1][lane + 96] = c3 * inv;
        if (lane == 0)
            g_pos[run][k1] = (u1 >= 0) ? ((const float2*)pos)[u1] : make_float2(0.f, 0.f);
    }
}

// ---------------- kernel 2: lower-triangle pair sums ----------------
// 64x64 tiles, 256 threads, 4x4 micro-tiles. All lanes busy.
#define TI 64
#define NT 8              // KPAD / TI
#define NTILE 36          // NT*(NT+1)/2
#define YSTR 132          // padded row stride (floats)
#define SMEM_BYTES (2 * TI * YSTR * 4 + 2 * TI * 8)

__global__ void __launch_bounds__(256, 3) k_pairs() {
    extern __shared__ float sm[];
    float* syi = sm;
    float* syj = sm + TI * YSTR;
    float2* sp = (float2*)(sm + 2 * TI * YSTR);   // [0..63]=pos_i, [64..127]=pos_j

    int run = blockIdx.x / NTILE;
    int t   = blockIdx.x % NTILE;
    int ti = 0;
    while ((ti + 1) * (ti + 2) / 2 <= t) ti++;
    int tj = t - ti * (ti + 1) / 2;
    int i0 = ti * TI, j0 = tj * TI;

    for (int idx = threadIdx.x; idx < TI * 32; idx += blockDim.x) {
        int r = idx >> 5, c4 = idx & 31;
        float4 vi = ((const float4*)&g_y[run][i0 + r][0])[c4];
        ((float4*)&syi[r * YSTR])[c4] = vi;
        float4 vj = ((const float4*)&g_y[run][j0 + r][0])[c4];
        ((float4*)&syj[r * YSTR])[c4] = vj;
    }
    if (threadIdx.x < TI)          sp[threadIdx.x] = g_pos[run][i0 + threadIdx.x];
    else if (threadIdx.x < 2 * TI) sp[threadIdx.x] = g_pos[run][j0 + threadIdx.x - TI];
    __syncthreads();

    int tid = threadIdx.x;
    int ty = tid >> 4, tx = tid & 15;      // 16x16 thread grid

    float acc[4][4];
#pragma unroll
    for (int a = 0; a < 4; a++)
#pragma unroll
        for (int b = 0; b < 4; b++) acc[a][b] = 0.f;

#pragma unroll 4
    for (int c = 0; c < 32; c++) {
        float4 A[4], Bv[4];
#pragma unroll
        for (int a = 0; a < 4; a++) A[a]  = ((float4*)&syi[(ty * 4 + a) * YSTR])[c];
#pragma unroll
        for (int b = 0; b < 4; b++) Bv[b] = ((float4*)&syj[(tx * 4 + b) * YSTR])[c];
#pragma unroll
        for (int a = 0; a < 4; a++)
#pragma unroll
            for (int b = 0; b < 4; b++) {
                acc[a][b] += A[a].x * Bv[b].x + A[a].y * Bv[b].y
                           + A[a].z * Bv[b].z + A[a].w * Bv[b].w;
            }
    }

    float sr = 0.f, srr = 0.f, srd = 0.f, sd = 0.f, sdd = 0.f;
#pragma unroll
    for (int a = 0; a < 4; a++) {
#pragma unroll
        for (int b = 0; b < 4; b++) {
            int i = i0 + ty * 4 + a;
            int j = j0 + tx * 4 + b;
            if (i < KK && j < i) {          // tril(k=-1); pad rows excluded
                float2 P = sp[ty * 4 + a];
                float2 Q = sp[TI + tx * 4 + b];
                float dx = P.x - Q.x, dy = P.y - Q.y;
                float dist = sqrtf(dx * dx + dy * dy);
                float ds = 1.0f / (dist + 1.0f);
                float rv = acc[a][b];
                sr  += rv;      srr += rv * rv;  srd += rv * ds;
                sd  += ds;      sdd += ds * ds;
            }
        }
    }

    float vals[5] = {sr, srr, srd, sd, sdd};
    __shared__ double red[8][5];
    int lane = tid & 31, wid = tid >> 5;
#pragma unroll
    for (int v = 0; v < 5; v++) {
        float x = vals[v];
#pragma unroll
        for (int o = 16; o; o >>= 1) x += __shfl_xor_sync(0xFFFFFFFFu, x, o);
        if (lane == 0) red[wid][v] = (double)x;
    }
    __syncthreads();
    if (tid < 5) {
        double s = 0.0;
#pragma unroll
        for (int w = 0; w < 8; w++) s += red[w][tid];
        atomicAdd(&g_acc[run][tid], s);
    }
}

// ---------------- kernel 3: finalize ----------------
__global__ void k_final(float* __restrict__ out) {
    __shared__ double losses[NRUNS];
    int r = threadIdx.x;
    if (r < NRUNS) {
        const double P = (double)(KK * (KK - 1) / 2);
        double Sr  = g_acc[r][0], Srr = g_acc[r][1], Srd = g_acc[r][2];
        double Sd  = g_acc[r][3], Sdd = g_acc[r][4];
        double num = Srd - Sr * Sd / P;
        double den = sqrt((Srr - Sr * Sr / P) * (Sdd - Sd * Sd / P));
        losses[r] = (1.0 - num / den) * 0.5;
    }
    __syncthreads();
    if (threadIdx.x == 0) {
        double s = 0.0;
        for (int i = 0; i < NRUNS; i++) s += losses[i];
        out[0] = (float)(s / NRUNS);
    }
}

// ---------------- launch ----------------
extern "C" void kernel_launch(void* const* d_in, const int* in_sizes, int n_in,
                              void* d_out, int out_size) {
    const float* feats = (const float*)d_in[0];   // (128, 100000) f32
    const float* pos   = (const float*)d_in[1];   // (100000, 2)   f32
    const int*   neigh = (const int*)  d_in[2];   // (100, 500)    i32

    cudaFuncSetAttribute(k_pairs, cudaFuncAttributeMaxDynamicSharedMemorySize,
                         SMEM_BYTES);

    k_gather<<<dim3(32, NRUNS), 256>>>(feats, pos, neigh);
    k_pairs<<<NRUNS * NTILE, 256, SMEM_BYTES>>>();
    k_final<<<1, 32>>>((float*)d_out);
}

// round 6
// speedup vs baseline: 1.3530x; 1.3530x over previous
#include <cuda_runtime.h>
#include <cuda_bf16.h>
#include <math.h>

#define UU 100000
#define BB 128
#define KK 500
#define KPAD 512
#define NNBH 100
#define NRUNS 10

// ---------------- scratch (no allocations allowed) ----------------
__device__ float  g_yt[NRUNS][BB][KPAD];  // TRANSPOSED: [c][k], centered+normalized
__device__ float2 g_pos[NRUNS][KPAD];
__device__ int    g_uord[NRUNS][KPAD];    // sorted chosen indices (pads = INT_MAX)
__device__ double g_acc[NRUNS][5];        // Sr, Srr, Srd, Sd, Sdd

// ---------------- threefry2x32 (JAX legacy layout — validated R2) ----------------
__device__ __forceinline__ unsigned rotl32(unsigned x, int r) {
    return (x << r) | (x >> (32 - r));
}

__device__ __forceinline__ void tf2x32(unsigned x0, unsigned x1,
                                       unsigned& o0, unsigned& o1) {
    const unsigned k0 = 0u, k1 = 42u;
    const unsigned k2 = k0 ^ k1 ^ 0x1BD11BDAu;
    x0 += k0; x1 += k1;
    const int rotA[4] = {13, 15, 26, 6};
    const int rotB[4] = {17, 29, 16, 24};
#pragma unroll
    for (int i = 0; i < 4; i++) { x0 += x1; x1 = rotl32(x1, rotA[i]); x1 ^= x0; }
    x0 += k1; x1 += k2 + 1u;
#pragma unroll
    for (int i = 0; i < 4; i++) { x0 += x1; x1 = rotl32(x1, rotB[i]); x1 ^= x0; }
    x0 += k2; x1 += k0 + 2u;
#pragma unroll
    for (int i = 0; i < 4; i++) { x0 += x1; x1 = rotl32(x1, rotA[i]); x1 ^= x0; }
    x0 += k0; x1 += k1 + 3u;
#pragma unroll
    for (int i = 0; i < 4; i++) { x0 += x1; x1 = rotl32(x1, rotB[i]); x1 ^= x0; }
    x0 += k1; x1 += k2 + 4u;
#pragma unroll
    for (int i = 0; i < 4; i++) { x0 += x1; x1 = rotl32(x1, rotA[i]); x1 ^= x0; }
    x0 += k2; x1 += k0 + 5u;
    o0 = x0; o1 = x1;
}

__device__ __forceinline__ unsigned choice_for(int r) {
    unsigned a0, a1;
    tf2x32((unsigned)r, (unsigned)(r + NRUNS), a0, a1);
    return ((a0 % 100u) * 96u + (a1 % 100u)) % 100u;   // (2^16%100)^2%100 = 96
}

// ---------------- kernel 0: pick choice, gather u's, bitonic sort ----------------
// Pair-set Pearson is permutation-invariant, so sorted order is valid and gives
// DRAM row locality in the gather.
__global__ void __launch_bounds__(KPAD) k_sort(const int* __restrict__ neigh) {
    __shared__ int sv[KPAD];
    int run = blockIdx.x;
    int t = threadIdx.x;
    __shared__ int s_choice;
    if (t == 0) s_choice = (int)choice_for(run);
    if (t < 5) g_acc[run][t] = 0.0;
    __syncthreads();
    int choice = s_choice;
    sv[t] = (t < KK) ? __ldg(&neigh[choice * KK + t]) : 0x7FFFFFFF;
    __syncthreads();
    for (int k = 2; k <= KPAD; k <<= 1) {
        for (int j = k >> 1; j > 0; j >>= 1) {
            int ixj = t ^ j;
            if (ixj > t) {
                int a = sv[t], b = sv[ixj];
                bool up = ((t & k) == 0);
                if ((a > b) == up) { sv[t] = b; sv[ixj] = a; }
            }
            __syncthreads();
        }
    }
    g_uord[run][t] = sv[t];
}

// ---------------- kernel 1: gather + center + normalize + TRANSPOSE ----------------
// grid (32, NRUNS) x 256. Warp w handles k0 = bx*16 + 2w and k0+1.
// Results staged in smem [128][17] then written c-major to g_yt.
__global__ void __launch_bounds__(256) k_gather(const float* __restrict__ feats,
                                                const float* __restrict__ pos) {
    __shared__ float stage[BB][17];   // [c][local k 0..15], pad 17 -> conflict-free
    int run = blockIdx.y;
    int warp = threadIdx.x >> 5, lane = threadIdx.x & 31;
    int kbase = blockIdx.x * 16;
    int k0 = kbase + warp * 2;
    int k1 = k0 + 1;

    int u0 = (k0 < KK) ? __ldg(&g_uord[run][k0]) : 0x7FFFFFFF;
    int u1 = (k1 < KK) ? __ldg(&g_uord[run][k1]) : 0x7FFFFFFF;
    bool v0ok = (u0 < UU), v1ok = (u1 < UU);

    float a0 = 0.f, a1 = 0.f, a2 = 0.f, a3 = 0.f;
    float b0 = 0.f, b1 = 0.f, b2 = 0.f, b3 = 0.f;
    if (v0ok) {
        a0 = __ldg(&feats[(size_t)(lane      ) * UU + u0]);
        a1 = __ldg(&feats[(size_t)(lane + 32) * UU + u0]);
        a2 = __ldg(&feats[(size_t)(lane + 64) * UU + u0]);
        a3 = __ldg(&feats[(size_t)(lane + 96) * UU + u0]);
    }
    if (v1ok) {
        b0 = __ldg(&feats[(size_t)(lane      ) * UU + u1]);
        b1 = __ldg(&feats[(size_t)(lane + 32) * UU + u1]);
        b2 = __ldg(&feats[(size_t)(lane + 64) * UU + u1]);
        b3 = __ldg(&feats[(size_t)(lane + 96) * UU + u1]);
    }

    {   // k0
        float s = a0 + a1 + a2 + a3;
#pragma unroll
        for (int o = 16; o; o >>= 1) s += __shfl_xor_sync(0xFFFFFFFFu, s, o);
        float mean = s * (1.0f / 128.0f);
        float c0 = a0 - mean, c1 = a1 - mean, c2 = a2 - mean, c3 = a3 - mean;
        float ss = c0 * c0 + c1 * c1 + c2 * c2 + c3 * c3;
#pragma unroll
        for (int o = 16; o; o >>= 1) ss += __shfl_xor_sync(0xFFFFFFFFu, ss, o);
        float inv = v0ok ? rsqrtf(ss) : 0.0f;
        int lk = warp * 2;
        stage[lane     ][lk] = c0 * inv;
        stage[lane + 32][lk] = c1 * inv;
        stage[lane + 64][lk] = c2 * inv;
        stage[lane + 96][lk] = c3 * inv;
        if (lane == 0)
            g_pos[run][k0] = v0ok ? ((const float2*)pos)[u0] : make_float2(0.f, 0.f);
    }
    {   // k1
        float s = b0 + b1 + b2 + b3;
#pragma unroll
        for (int o = 16; o; o >>= 1) s += __shfl_xor_sync(0xFFFFFFFFu, s, o);
        float mean = s * (1.0f / 128.0f);
        float c0 = b0 - mean, c1 = b1 - mean, c2 = b2 - mean, c3 = b3 - mean;
        float ss = c0 * c0 + c1 * c1 + c2 * c2 + c3 * c3;
#pragma unroll
        for (int o = 16; o; o >>= 1) ss += __shfl_xor_sync(0xFFFFFFFFu, ss, o);
        float inv = v1ok ? rsqrtf(ss) : 0.0f;
        int lk = warp * 2 + 1;
        stage[lane     ][lk] = c0 * inv;
        stage[lane + 32][lk] = c1 * inv;
        stage[lane + 64][lk] = c2 * inv;
        stage[lane + 96][lk] = c3 * inv;
        if (lane == 0)
            g_pos[run][k1] = v1ok ? ((const float2*)pos)[u1] : make_float2(0.f, 0.f);
    }
    __syncthreads();

    // write-out: c-major, 16 k's per c. thread t: c = t>>1, half = t&1 (8 k's each)
    int c = threadIdx.x >> 1, half = threadIdx.x & 1;
    float4 o0, o1;
    o0.x = stage[c][half * 8 + 0]; o0.y = stage[c][half * 8 + 1];
    o0.z = stage[c][half * 8 + 2]; o0.w = stage[c][half * 8 + 3];
    o1.x = stage[c][half * 8 + 4]; o1.y = stage[c][half * 8 + 5];
    o1.z = stage[c][half * 8 + 6]; o1.w = stage[c][half * 8 + 7];
    float* dst = &g_yt[run][c][kbase + half * 8];
    ((float4*)dst)[0] = o0;
    ((float4*)dst)[1] = o1;
}

// ---------------- kernel 2: lower-triangle pair sums (c-major, conflict-free) ----
#define TI 64
#define NT 8              // KPAD / TI
#define NTILE 36          // NT*(NT+1)/2
// smem: two tiles of [128 c][16 float4] + positions
#define SMEM_BYTES (2 * BB * 16 * 16 + 2 * TI * 8)

__global__ void __launch_bounds__(256, 3) k_pairs() {
    extern __shared__ float sm[];
    float4* syi = (float4*)sm;                 // [c][q] q=0..15 (64 rows)
    float4* syj = (float4*)(sm + BB * 16 * 4);
    float2* sp  = (float2*)(sm + 2 * BB * 16 * 4);

    int run = blockIdx.x / NTILE;
    int t   = blockIdx.x % NTILE;
    int ti = 0;
    while ((ti + 1) * (ti + 2) / 2 <= t) ti++;
    int tj = t - ti * (ti + 1) / 2;
    int i0 = ti * TI, j0 = tj * TI;

    // load phase: coalesced reads (256B contiguous per c), conflict-free stores
    for (int idx = threadIdx.x; idx < BB * 16; idx += blockDim.x) {
        int c = idx >> 4, q = idx & 15;
        syi[c * 16 + q] = *(const float4*)&g_yt[run][c][i0 + 4 * q];
        syj[c * 16 + q] = *(const float4*)&g_yt[run][c][j0 + 4 * q];
    }
    if (threadIdx.x < TI)          sp[threadIdx.x] = g_pos[run][i0 + threadIdx.x];
    else if (threadIdx.x < 2 * TI) sp[threadIdx.x] = g_pos[run][j0 + threadIdx.x - TI];
    __syncthreads();

    int tid = threadIdx.x;
    int ty = tid >> 4, tx = tid & 15;      // 16x16 thread grid, 4x4 micro-tile

    float acc[4][4];
#pragma unroll
    for (int a = 0; a < 4; a++)
#pragma unroll
        for (int b = 0; b < 4; b++) acc[a][b] = 0.f;

    const float4* pA = syi + ty;
    const float4* pB = syj + tx;
#pragma unroll 8
    for (int c = 0; c < BB; c++) {
        float4 A = pA[c * 16];   // rows ty*4..ty*4+3 at this c
        float4 B = pB[c * 16];   // rows tx*4..tx*4+3 at this c
        acc[0][0] += A.x * B.x; acc[0][1] += A.x * B.y; acc[0][2] += A.x * B.z; acc[0][3] += A.x * B.w;
        acc[1][0] += A.y * B.x; acc[1][1] += A.y * B.y; acc[1][2] += A.y * B.z; acc[1][3] += A.y * B.w;
        acc[2][0] += A.z * B.x; acc[2][1] += A.z * B.y; acc[2][2] += A.z * B.z; acc[2][3] += A.z * B.w;
        acc[3][0] += A.w * B.x; acc[3][1] += A.w * B.y; acc[3][2] += A.w * B.z; acc[3][3] += A.w * B.w;
    }

    float sr = 0.f, srr = 0.f, srd = 0.f, sd = 0.f, sdd = 0.f;
#pragma unroll
    for (int a = 0; a < 4; a++) {
#pragma unroll
        for (int b = 0; b < 4; b++) {
            int i = i0 + ty * 4 + a;
            int j = j0 + tx * 4 + b;
            if (i < KK && j < i) {          // tril over permuted (sorted) indices
                float2 P = sp[ty * 4 + a];
                float2 Q = sp[TI + tx * 4 + b];
                float dx = P.x - Q.x, dy = P.y - Q.y;
                float dist = sqrtf(dx * dx + dy * dy);
                float ds = 1.0f / (dist + 1.0f);
                float rv = acc[a][b];
                sr  += rv;      srr += rv * rv;  srd += rv * ds;
                sd  += ds;      sdd += ds * ds;
            }
        }
    }

    float vals[5] = {sr, srr, srd, sd, sdd};
    __shared__ double red[8][5];
    int lane = tid & 31, wid = tid >> 5;
#pragma unroll
    for (int v = 0; v < 5; v++) {
        float x = vals[v];
#pragma unroll
        for (int o = 16; o; o >>= 1) x += __shfl_xor_sync(0xFFFFFFFFu, x, o);
        if (lane == 0) red[wid][v] = (double)x;
    }
    __syncthreads();
    if (tid < 5) {
        double s = 0.0;
#pragma unroll
        for (int w = 0; w < 8; w++) s += red[w][tid];
        atomicAdd(&g_acc[run][tid], s);
    }
}

// ---------------- kernel 3: finalize ----------------
__global__ void k_final(float* __restrict__ out) {
    __shared__ double losses[NRUNS];
    int r = threadIdx.x;
    if (r < NRUNS) {
        const double P = (double)(KK * (KK - 1) / 2);
        double Sr  = g_acc[r][0], Srr = g_acc[r][1], Srd = g_acc[r][2];
        double Sd  = g_acc[r][3], Sdd = g_acc[r][4];
        double num = Srd - Sr * Sd / P;
        double den = sqrt((Srr - Sr * Sr / P) * (Sdd - Sd * Sd / P));
        losses[r] = (1.0 - num / den) * 0.5;
    }
    __syncthreads();
    if (threadIdx.x == 0) {
        double s = 0.0;
        for (int i = 0; i < NRUNS; i++) s += losses[i];
        out[0] = (float)(s / NRUNS);
    }
}

// ---------------- launch ----------------
extern "C" void kernel_launch(void* const* d_in, const int* in_sizes, int n_in,
                              void* d_out, int out_size) {
    const float* feats = (const float*)d_in[0];   // (128, 100000) f32
    const float* pos   = (const float*)d_in[1];   // (100000, 2)   f32
    const int*   neigh = (const int*)  d_in[2];   // (100, 500)    i32

    cudaFuncSetAttribute(k_pairs, cudaFuncAttributeMaxDynamicSharedMemorySize,
                         SMEM_BYTES);

    k_sort<<<NRUNS, KPAD>>>(neigh);
    k_gather<<<dim3(32, NRUNS), 256>>>(feats, pos);
    k_pairs<<<NRUNS * NTILE, 256, SMEM_BYTES>>>();
    k_final<<<1, 32>>>((float*)d_out);
}